// round 1
// baseline (speedup 1.0000x reference)
#include <cuda_runtime.h>

// patchEmbedding: B=32, T=4096, H=W=512, CH=1, P=16, EMB=768, FLAT=256, PAD=12
// out[b,t,0,e] = sum_{r,c} img[b, y0+r-12, x0+c-12] * W[e, r*16+c] + bias[e]
//   with y0 = kp_y + sh_y, x0 = kp_x + sh_x (out-of-image reads are zero).
//
// GEMM view: M = B*T = 131072, K = 256, N = 768.
// Tiling: 64(M) x 64(N) per 256-thread block, BK = 16 (= one patch row).

#define PADC   12
#define HW     512
#define TDIM   4096
#define EMBD   768
#define KTOT   256
#define BM     64
#define BN     64
#define BK     16

__global__ __launch_bounds__(256, 4)
void patch_embed_kernel(const float* __restrict__ img,
                        const int*   __restrict__ kp,
                        const int*   __restrict__ sh,
                        const float* __restrict__ W,
                        const float* __restrict__ bias,
                        float*       __restrict__ out)
{
    __shared__ float As[BK][BM];   // k-major A tile
    __shared__ float Bs[BK][BN];   // k-major B tile (W transposed into k-major)
    __shared__ int   sy[BM];
    __shared__ int   sx[BM];

    const int tid = threadIdx.x;
    const int m0  = blockIdx.y * BM;     // patch-row base (b*T + t)
    const int n0  = blockIdx.x * BN;     // embedding-col base

    // Per-patch start coords (already offset by -PAD into the *unpadded* image).
    if (tid < BM) {
        int m = m0 + tid;
        int2 k = ((const int2*)kp)[m];
        int2 s = ((const int2*)sh)[m];
        sx[tid] = k.x + s.x - PADC;      // starts[...,0] is x
        sy[tid] = k.y + s.y - PADC;      // starts[...,1] is y
    }

    // All 64 patches of this tile belong to one batch image (T % BM == 0).
    const float* imgb = img + (size_t)(m0 / TDIM) * (HW * HW);

    // Loader roles
    const int p  = tid >> 2;             // 0..63 : patch within tile / W row within tile
    const int q  = tid & 3;              // 0..3  : 4-float chunk within the 16-wide k-chunk
    const float4* wrow = (const float4*)(W + (size_t)(n0 + p) * KTOT);

    // Compute roles: 4x4 micro-tile
    const int ty = tid >> 4;             // 0..15 -> rows ty*4..ty*4+3
    const int tx = tid & 15;             // 0..15 -> cols tx*4..tx*4+3

    float acc[4][4] = {};

    __syncthreads();                     // sy/sx visible

    #pragma unroll 1
    for (int kc = 0; kc < KTOT / BK; kc++) {
        // ---- global loads for this k-chunk (patch row kc) ----
        const int gy  = sy[p] + kc;
        const int gx0 = sx[p] + q * 4;
        float v0 = 0.f, v1 = 0.f, v2 = 0.f, v3 = 0.f;
        if ((unsigned)gy < (unsigned)HW) {
            const float* rp = imgb + gy * HW;
            if ((unsigned)(gx0 + 0) < (unsigned)HW) v0 = rp[gx0 + 0];
            if ((unsigned)(gx0 + 1) < (unsigned)HW) v1 = rp[gx0 + 1];
            if ((unsigned)(gx0 + 2) < (unsigned)HW) v2 = rp[gx0 + 2];
            if ((unsigned)(gx0 + 3) < (unsigned)HW) v3 = rp[gx0 + 3];
        }
        const float4 w = wrow[kc * 4 + q];   // 16B-aligned, coalesced

        __syncthreads();                 // previous iteration's smem reads done

        As[q * 4 + 0][p] = v0;
        As[q * 4 + 1][p] = v1;
        As[q * 4 + 2][p] = v2;
        As[q * 4 + 3][p] = v3;
        Bs[q * 4 + 0][p] = w.x;
        Bs[q * 4 + 1][p] = w.y;
        Bs[q * 4 + 2][p] = w.z;
        Bs[q * 4 + 3][p] = w.w;

        __syncthreads();                 // tiles ready

        // ---- compute ----
        #pragma unroll
        for (int kk = 0; kk < BK; kk++) {
            const float4 a = *(const float4*)&As[kk][ty * 4];
            const float4 b = *(const float4*)&Bs[kk][tx * 4];
            acc[0][0] += a.x * b.x; acc[0][1] += a.x * b.y;
            acc[0][2] += a.x * b.z; acc[0][3] += a.x * b.w;
            acc[1][0] += a.y * b.x; acc[1][1] += a.y * b.y;
            acc[1][2] += a.y * b.z; acc[1][3] += a.y * b.w;
            acc[2][0] += a.z * b.x; acc[2][1] += a.z * b.y;
            acc[2][2] += a.z * b.z; acc[2][3] += a.z * b.w;
            acc[3][0] += a.w * b.x; acc[3][1] += a.w * b.y;
            acc[3][2] += a.w * b.z; acc[3][3] += a.w * b.w;
        }
    }

    // ---- epilogue: add bias, store float4 per row ----
    const float4 bl = *(const float4*)&bias[n0 + tx * 4];
    #pragma unroll
    for (int i = 0; i < 4; i++) {
        const size_t row = (size_t)(m0 + ty * 4 + i);
        float4 o;
        o.x = acc[i][0] + bl.x;
        o.y = acc[i][1] + bl.y;
        o.z = acc[i][2] + bl.z;
        o.w = acc[i][3] + bl.w;
        *(float4*)&out[row * EMBD + n0 + tx * 4] = o;
    }
}

extern "C" void kernel_launch(void* const* d_in, const int* in_sizes, int n_in,
                              void* d_out, int out_size)
{
    const float* img  = (const float*)d_in[0];   // [32,1,512,512] f32
    const int*   kp   = (const int*)  d_in[1];   // [32,4096,2] i32
    const int*   sh   = (const int*)  d_in[2];   // [32,4096,2] i32
    const float* Wlin = (const float*)d_in[3];   // [768,256] f32
    const float* blin = (const float*)d_in[4];   // [768] f32
    float*       out  = (float*)d_out;           // [32,4096,1,768] f32

    const int M = 32 * TDIM;                     // 131072
    dim3 grid(EMBD / BN, M / BM);                // (12, 2048)
    patch_embed_kernel<<<grid, 256>>>(img, kp, sh, Wlin, blin, out);
}

// round 3
// speedup vs baseline: 3.8905x; 3.8905x over previous
#include <cuda_runtime.h>
#include <cstdint>

// patchEmbedding as tf32 mma.sync GEMM (sm_103 plain target: no tcgen05 available)
//   M = B*T = 131072, K = 256 (16x16 patch), N = 768 (EMB)
//   A[m][k] = img[b, sy + k/16, sx + k%16] (zero OOB), sy/sx = kp+shift-12
//   B[n][k] = Wlin[n][k];  out[m][n] = sum_k A*B + bias[n]
// Tile: BM=128 x BN=128 per 256-thread CTA, BK=32 (two patch rows), double-buffered.

#define HW    512
#define TDIM  4096
#define EMBD  768
#define KTOT  256
#define BM    128
#define BN    128
#define BK    32
#define NKC   8
#define PADC  12

#define ASTRIDE 36                       // floats per smem row (pad 32->36: conflict-free frags)
#define STAGE   (128 * ASTRIDE * 4)      // 18432 B per stage (A or B)

#define SM_COORD 0                       // 128 * int2 = 1024 B
#define SM_A     1024                    // 2 stages
#define SM_B     (SM_A + 2 * STAGE)
#define SM_TOTAL (SM_B + 2 * STAGE)      // 74752 B

__device__ __align__(16) float g_Wtf[EMBD * KTOT];   // tf32-pre-rounded Wlin

__device__ __forceinline__ float tf32r(float x) {
    float y;
    asm("cvt.rna.tf32.f32 %0, %1;" : "=f"(y) : "f"(x));
    return y;
}
__device__ __forceinline__ uint32_t s2u(const void* p) {
    uint32_t a;
    asm("{ .reg .u64 t; cvta.to.shared.u64 t, %1; cvt.u32.u64 %0, t; }" : "=r"(a) : "l"(p));
    return a;
}
__device__ __forceinline__ void cp16(uint32_t dst, const float* src) {
    asm volatile("cp.async.ca.shared.global [%0], [%1], 16;" :: "r"(dst), "l"(src) : "memory");
}
__device__ __forceinline__ void mma_tf32(float c[4], const uint32_t a[4],
                                         uint32_t b0, uint32_t b1) {
    asm volatile(
        "mma.sync.aligned.m16n8k8.row.col.f32.tf32.tf32.f32 "
        "{%0,%1,%2,%3}, {%4,%5,%6,%7}, {%8,%9}, {%0,%1,%2,%3};"
        : "+f"(c[0]), "+f"(c[1]), "+f"(c[2]), "+f"(c[3])
        : "r"(a[0]), "r"(a[1]), "r"(a[2]), "r"(a[3]), "r"(b0), "r"(b1));
}

__global__ void prep_w(const float* __restrict__ W) {
    int i = blockIdx.x * blockDim.x + threadIdx.x;
    if (i < EMBD * KTOT) g_Wtf[i] = tf32r(W[i]);
}

__global__ void __launch_bounds__(256, 2)
patch_embed_mma(const float* __restrict__ img,
                const int*   __restrict__ kp,
                const int*   __restrict__ sh,
                const float* __restrict__ bias,
                float*       __restrict__ out)
{
    extern __shared__ char smem[];
    const uint32_t sb = s2u(smem);
    const int tid = threadIdx.x;
    const int wid = tid >> 5;
    const int lid = tid & 31;
    const int m0  = blockIdx.y * BM;
    const int n0  = blockIdx.x * BN;

    const int wm = wid & 3;              // 4 m-groups of 32 rows
    const int wn = wid >> 2;             // 2 n-groups of 64 cols
    const int gq = lid >> 2;             // 0..7  (fragment row group)
    const int tq = lid & 3;              // 0..3  (fragment col in group)

    // patch start coords (offset -PAD into the unpadded image)
    int2* coord = (int2*)(smem + SM_COORD);
    if (tid < BM) {
        int2 k = ((const int2*)kp)[m0 + tid];
        int2 s = ((const int2*)sh)[m0 + tid];
        int2 c;
        c.x = k.x + s.x - PADC;          // starts[...,0] = x
        c.y = k.y + s.y - PADC;          // starts[...,1] = y
        coord[tid] = c;
    }
    __syncthreads();

    const float* imgb = img + (size_t)(m0 / TDIM) * (HW * HW);
    const int h = (lid >> 4);            // which of the 2 image rows in this k-chunk
    const int j = lid & 15;              // pixel within row

    float acc[2][8][4] = {};
    float areg[16];

    // ---- helpers (expanded inline) ----
    #define GATHER_A(kc)                                                          \
        _Pragma("unroll")                                                         \
        for (int i = 0; i < 16; i++) {                                            \
            const int p = i * 8 + wid;                                            \
            const int2 c = coord[p];                                              \
            const int y = c.y + (kc) * 2 + h;                                     \
            const int x = c.x + j;                                                \
            float v = 0.f;                                                        \
            if (((unsigned)y < HW) && ((unsigned)x < HW))                         \
                v = __ldg(imgb + y * HW + x);                                     \
            areg[i] = tf32r(v);                                                   \
        }

    #define STS_A(buf)                                                            \
        {                                                                         \
            float* Aw = (float*)(smem + SM_A + (buf) * STAGE);                    \
            _Pragma("unroll")                                                     \
            for (int i = 0; i < 16; i++)                                          \
                Aw[(i * 8 + wid) * ASTRIDE + h * 16 + j] = areg[i];               \
        }

    #define LOAD_B(buf, kc)                                                       \
        {                                                                         \
            _Pragma("unroll")                                                     \
            for (int i = 0; i < 4; i++) {                                         \
                const int idx = i * 256 + tid;                                    \
                const int row = idx >> 3;                                         \
                const int q   = idx & 7;                                          \
                cp16(sb + SM_B + (buf) * STAGE + row * (ASTRIDE * 4) + q * 16,    \
                     g_Wtf + (size_t)(n0 + row) * KTOT + (kc) * BK + q * 4);      \
            }                                                                     \
            asm volatile("cp.async.commit_group;" ::: "memory");                  \
        }

    // ---- prologue: stage 0 ----
    LOAD_B(0, 0);
    GATHER_A(0);
    STS_A(0);

    #pragma unroll 1
    for (int kc = 0; kc < NKC; kc++) {
        const int cur = kc & 1;
        asm volatile("cp.async.wait_group 0;" ::: "memory");
        __syncthreads();                           // stage `cur` ready; buffer cur^1 free

        if (kc + 1 < NKC) {
            LOAD_B(cur ^ 1, kc + 1);               // overlaps with compute below
            GATHER_A(kc + 1);
        }

        const float* Asf = (const float*)(smem + SM_A + cur * STAGE);
        const float* Bsf = (const float*)(smem + SM_B + cur * STAGE);

        #pragma unroll
        for (int ks = 0; ks < 4; ks++) {
            const int k0 = ks * 8;
            uint32_t a[2][4];
            #pragma unroll
            for (int mt = 0; mt < 2; mt++) {
                const int r = wm * 32 + mt * 16 + gq;
                a[mt][0] = *(const uint32_t*)&Asf[r * ASTRIDE + k0 + tq];
                a[mt][1] = *(const uint32_t*)&Asf[(r + 8) * ASTRIDE + k0 + tq];
                a[mt][2] = *(const uint32_t*)&Asf[r * ASTRIDE + k0 + tq + 4];
                a[mt][3] = *(const uint32_t*)&Asf[(r + 8) * ASTRIDE + k0 + tq + 4];
            }
            #pragma unroll
            for (int nt = 0; nt < 8; nt++) {
                const int n = wn * 64 + nt * 8 + gq;
                const uint32_t b0 = *(const uint32_t*)&Bsf[n * ASTRIDE + k0 + tq];
                const uint32_t b1 = *(const uint32_t*)&Bsf[n * ASTRIDE + k0 + tq + 4];
                mma_tf32(acc[0][nt], a[0], b0, b1);
                mma_tf32(acc[1][nt], a[1], b0, b1);
            }
        }

        if (kc + 1 < NKC) STS_A(cur ^ 1);
    }

    // ---- epilogue: bias + store (float2 per fragment half) ----
    #pragma unroll
    for (int mt = 0; mt < 2; mt++) {
        const int r0 = m0 + wm * 32 + mt * 16 + gq;
        #pragma unroll
        for (int nt = 0; nt < 8; nt++) {
            const int col = n0 + wn * 64 + nt * 8 + tq * 2;
            const float2 bl = *(const float2*)(bias + col);
            float2 o0, o1;
            o0.x = acc[mt][nt][0] + bl.x;
            o0.y = acc[mt][nt][1] + bl.y;
            o1.x = acc[mt][nt][2] + bl.x;
            o1.y = acc[mt][nt][3] + bl.y;
            *(float2*)(out + (size_t)r0 * EMBD + col)       = o0;
            *(float2*)(out + (size_t)(r0 + 8) * EMBD + col) = o1;
        }
    }
}

extern "C" void kernel_launch(void* const* d_in, const int* in_sizes, int n_in,
                              void* d_out, int out_size)
{
    const float* img  = (const float*)d_in[0];   // [32,1,512,512] f32
    const int*   kp   = (const int*)  d_in[1];   // [32,4096,2] i32
    const int*   sh   = (const int*)  d_in[2];   // [32,4096,2] i32
    const float* Wlin = (const float*)d_in[3];   // [768,256] f32
    const float* blin = (const float*)d_in[4];   // [768] f32
    float*       out  = (float*)d_out;           // [32,4096,768] f32

    prep_w<<<(EMBD * KTOT + 255) / 256, 256>>>(Wlin);

    cudaFuncSetAttribute(patch_embed_mma,
                         cudaFuncAttributeMaxDynamicSharedMemorySize, SM_TOTAL);
    dim3 grid(EMBD / BN, (32 * TDIM) / BM);      // (6, 1024)
    patch_embed_mma<<<grid, 256, SM_TOTAL>>>(img, kp, sh, blin, out);
}

// round 4
// speedup vs baseline: 4.0862x; 1.0503x over previous
#include <cuda_runtime.h>
#include <cstdint>

// patchEmbedding, split into: (0) W tf32-prep, (1) patch gather/pack, (2) dense tf32 HMMA GEMM.
//   M = B*T = 131072, K = 256, N = 768 (EMB)
// K layout is pair-permuted per 8-group: pos' = 2*(pos&3) + (pos>>2), so mma fragment
// operand pairs (k, k+4) are adjacent -> LDS.64 fragment loads.

#define HW    512
#define TDIM  4096
#define EMBD  768
#define KTOT  256
#define BM    128
#define BN    128
#define BK    32
#define NKC   8
#define PADC  12

#define ASTRIDE 40                        // floats per smem row (conflict-free LDS.64 frags)
#define MATB    (128 * ASTRIDE * 4)       // 20480 B per matrix per stage

#define SM_A     0                        // A stages 0,1
#define SM_B     (2 * MATB)               // B stages 0,1
#define SM_TOTAL (4 * MATB)               // 81920 B

__device__ __align__(16) float g_Wtf[EMBD * KTOT];           // tf32, k-permuted
__device__ __align__(16) float g_Apack[131072 * KTOT];       // tf32, k-permuted

__device__ __forceinline__ float tf32r(float x) {
    float y;
    asm("cvt.rna.tf32.f32 %0, %1;" : "=f"(y) : "f"(x));
    return y;
}
__device__ __forceinline__ uint32_t s2u(const void* p) {
    uint32_t a;
    asm("{ .reg .u64 t; cvta.to.shared.u64 t, %1; cvt.u32.u64 %0, t; }" : "=r"(a) : "l"(p));
    return a;
}
__device__ __forceinline__ void cp16(uint32_t dst, const float* src) {
    asm volatile("cp.async.ca.shared.global [%0], [%1], 16;" :: "r"(dst), "l"(src) : "memory");
}
__device__ __forceinline__ void mma_tf32(float c[4], uint32_t a0, uint32_t a1,
                                         uint32_t a2, uint32_t a3,
                                         uint32_t b0, uint32_t b1) {
    asm volatile(
        "mma.sync.aligned.m16n8k8.row.col.f32.tf32.tf32.f32 "
        "{%0,%1,%2,%3}, {%4,%5,%6,%7}, {%8,%9}, {%0,%1,%2,%3};"
        : "+f"(c[0]), "+f"(c[1]), "+f"(c[2]), "+f"(c[3])
        : "r"(a0), "r"(a1), "r"(a2), "r"(a3), "r"(b0), "r"(b1));
}

// ---- kernel 0: W -> tf32, k pair-permuted ----
__global__ void prep_w(const float* __restrict__ W) {
    int i = blockIdx.x * blockDim.x + threadIdx.x;
    if (i >= EMBD * KTOT) return;
    int k = i & (KTOT - 1);
    int pos = k & 7;
    int kp = (k & ~7) | (2 * (pos & 3) + (pos >> 2));
    g_Wtf[(i & ~(KTOT - 1)) | kp] = tf32r(W[i]);
}

// ---- kernel 1: gather patches -> g_Apack (tf32, k pair-permuted) ----
__global__ void __launch_bounds__(256, 4)
pack_a(const float* __restrict__ img,
       const int*   __restrict__ kp,
       const int*   __restrict__ sh)
{
    __shared__ int2 coord[BM];
    const int tid = threadIdx.x;
    const int wid = tid >> 5;
    const int lid = tid & 31;
    const int m0  = blockIdx.x * BM;

    if (tid < BM) {
        int2 k = ((const int2*)kp)[m0 + tid];
        int2 s = ((const int2*)sh)[m0 + tid];
        int2 c;
        c.x = k.x + s.x - PADC;          // starts[...,0] = x
        c.y = k.y + s.y - PADC;          // starts[...,1] = y
        coord[tid] = c;
    }
    __syncthreads();

    const float* imgb = img + (size_t)(m0 / TDIM) * (HW * HW);
    const int h = lid >> 4;              // row within the 2-row k-chunk
    const int j = lid & 15;              // pixel within row
    const int klocal = h * 16 + j;
    const int pos = klocal & 7;
    const int klp = (klocal & ~7) | (2 * (pos & 3) + (pos >> 2));   // permuted

    #pragma unroll 1
    for (int i = 0; i < 16; i++) {
        const int p = i * 8 + wid;
        const int2 c = coord[p];
        float* orow = g_Apack + (size_t)(m0 + p) * KTOT + klp;
        #pragma unroll
        for (int kc = 0; kc < NKC; kc++) {
            const int y = c.y + kc * 2 + h;
            const int x = c.x + j;
            float v = 0.f;
            if (((unsigned)y < HW) && ((unsigned)x < HW))
                v = __ldg(imgb + y * HW + x);
            orow[kc * BK] = tf32r(v);
        }
    }
}

// ---- kernel 2: dense GEMM out = Apack @ Wtf^T + bias ----
__global__ void __launch_bounds__(256, 2)
gemm_tc(const float* __restrict__ bias, float* __restrict__ out)
{
    extern __shared__ char smem[];
    const uint32_t sb = s2u(smem);
    const int tid = threadIdx.x;
    const int wid = tid >> 5;
    const int lid = tid & 31;
    const int m0  = blockIdx.y * BM;
    const int n0  = blockIdx.x * BN;

    const int wm = wid & 3;              // 4 m-groups of 32 rows
    const int wn = wid >> 2;             // 2 n-groups of 64 cols
    const int gq = lid >> 2;             // 0..7
    const int tq = lid & 3;              // 0..3

    const int lrow = tid >> 3;           // loader row (0..31 per 256/8... idx>>3 below)
    (void)lrow;

    float acc[2][8][4] = {};

    #define LOAD_STAGE(buf, kc)                                                   \
        {                                                                         \
            _Pragma("unroll")                                                     \
            for (int i = 0; i < 4; i++) {                                         \
                const int idx = i * 256 + tid;                                    \
                const int row = idx >> 3;                                         \
                const int q   = idx & 7;                                          \
                cp16(sb + SM_A + (buf) * MATB + row * (ASTRIDE * 4) + q * 16,     \
                     g_Apack + (size_t)(m0 + row) * KTOT + (kc) * BK + q * 4);    \
                cp16(sb + SM_B + (buf) * MATB + row * (ASTRIDE * 4) + q * 16,     \
                     g_Wtf + (size_t)(n0 + row) * KTOT + (kc) * BK + q * 4);      \
            }                                                                     \
            asm volatile("cp.async.commit_group;" ::: "memory");                  \
        }

    LOAD_STAGE(0, 0);
    LOAD_STAGE(1, 1);

    #pragma unroll 1
    for (int kc = 0; kc < NKC; kc++) {
        const int cur = kc & 1;
        if (kc == NKC - 1)
            asm volatile("cp.async.wait_group 0;" ::: "memory");
        else
            asm volatile("cp.async.wait_group 1;" ::: "memory");
        __syncthreads();

        const float* Asf = (const float*)(smem + SM_A + cur * MATB);
        const float* Bsf = (const float*)(smem + SM_B + cur * MATB);

        #pragma unroll
        for (int ks = 0; ks < 4; ks++) {
            const int k0 = ks * 8 + 2 * tq;              // permuted pair base
            uint2 a0[2], a1[2];
            #pragma unroll
            for (int mt = 0; mt < 2; mt++) {
                const int r = wm * 32 + mt * 16 + gq;
                a0[mt] = *(const uint2*)&Asf[r * ASTRIDE + k0];        // (a0, a2)
                a1[mt] = *(const uint2*)&Asf[(r + 8) * ASTRIDE + k0];  // (a1, a3)
            }
            #pragma unroll
            for (int nt = 0; nt < 8; nt++) {
                const int n = wn * 64 + nt * 8 + gq;
                const uint2 b = *(const uint2*)&Bsf[n * ASTRIDE + k0]; // (b0, b1)
                mma_tf32(acc[0][nt], a0[0].x, a1[0].x, a0[0].y, a1[0].y, b.x, b.y);
                mma_tf32(acc[1][nt], a0[1].x, a1[1].x, a0[1].y, a1[1].y, b.x, b.y);
            }
        }

        __syncthreads();
        if (kc + 2 < NKC) LOAD_STAGE(cur, kc + 2);
    }

    // ---- epilogue: bias + float2 stores ----
    #pragma unroll
    for (int mt = 0; mt < 2; mt++) {
        const int r0 = m0 + wm * 32 + mt * 16 + gq;
        #pragma unroll
        for (int nt = 0; nt < 8; nt++) {
            const int col = n0 + wn * 64 + nt * 8 + tq * 2;
            const float2 bl = *(const float2*)(bias + col);
            float2 o0, o1;
            o0.x = acc[mt][nt][0] + bl.x;
            o0.y = acc[mt][nt][1] + bl.y;
            o1.x = acc[mt][nt][2] + bl.x;
            o1.y = acc[mt][nt][3] + bl.y;
            *(float2*)(out + (size_t)r0 * EMBD + col)       = o0;
            *(float2*)(out + (size_t)(r0 + 8) * EMBD + col) = o1;
        }
    }
}

extern "C" void kernel_launch(void* const* d_in, const int* in_sizes, int n_in,
                              void* d_out, int out_size)
{
    const float* img  = (const float*)d_in[0];   // [32,1,512,512] f32
    const int*   kp   = (const int*)  d_in[1];   // [32,4096,2] i32
    const int*   sh   = (const int*)  d_in[2];   // [32,4096,2] i32
    const float* Wlin = (const float*)d_in[3];   // [768,256] f32
    const float* blin = (const float*)d_in[4];   // [768] f32
    float*       out  = (float*)d_out;           // [32,4096,768] f32

    prep_w<<<(EMBD * KTOT + 255) / 256, 256>>>(Wlin);
    pack_a<<<(32 * TDIM) / BM, 256>>>(img, kp, sh);

    cudaFuncSetAttribute(gemm_tc,
                         cudaFuncAttributeMaxDynamicSharedMemorySize, SM_TOTAL);
    dim3 grid(EMBD / BN, (32 * TDIM) / BM);      // (6, 1024)
    gemm_tc<<<grid, 256, SM_TOTAL>>>(blin, out);
}

// round 5
// speedup vs baseline: 6.5021x; 1.5912x over previous
#include <cuda_runtime.h>
#include <cuda_fp16.h>
#include <cstdint>

// patchEmbedding: (0) W->fp16 prep, (1) patch gather/pack fp16, (2) dense fp16 HMMA GEMM.
//   M = B*T = 131072, K = 256, N = 768
// K is pair-permuted per 16-group (pair p -> 2*(p&3)+(p>>2)) so each mma.m16n8k16
// fragment's half-pairs (2tq, 2tq+8) are adjacent -> single LDS.64 per fragment.

#define HW    512
#define TDIM  4096
#define EMBD  768
#define KTOT  256
#define BM    128
#define BN    128
#define BKH   64                          // halves per k-stage
#define NKC   4                           // 256 / 64
#define PADC  12

#define SROW  160                         // bytes per smem row (128B data + 32B pad)
#define MATB  (128 * SROW)                // 20480 B per matrix per stage
#define SM_A     0
#define SM_B     (2 * MATB)
#define SM_TOTAL (4 * MATB)               // 81920 B

__device__ __align__(16) __half g_Wh[EMBD * KTOT];        // fp16, k-permuted
__device__ __align__(16) __half g_Apack[131072 * KTOT];   // fp16, k-permuted

__device__ __forceinline__ uint32_t s2u(const void* p) {
    uint32_t a;
    asm("{ .reg .u64 t; cvta.to.shared.u64 t, %1; cvt.u32.u64 %0, t; }" : "=r"(a) : "l"(p));
    return a;
}
__device__ __forceinline__ void cp16(uint32_t dst, const void* src) {
    asm volatile("cp.async.ca.shared.global [%0], [%1], 16;" :: "r"(dst), "l"(src) : "memory");
}
__device__ __forceinline__ void mma_f16(float c[4], uint32_t a0, uint32_t a1,
                                        uint32_t a2, uint32_t a3,
                                        uint32_t b0, uint32_t b1) {
    asm volatile(
        "mma.sync.aligned.m16n8k16.row.col.f32.f16.f16.f32 "
        "{%0,%1,%2,%3}, {%4,%5,%6,%7}, {%8,%9}, {%0,%1,%2,%3};"
        : "+f"(c[0]), "+f"(c[1]), "+f"(c[2]), "+f"(c[3])
        : "r"(a0), "r"(a1), "r"(a2), "r"(a3), "r"(b0), "r"(b1));
}

// permute half index k within its 16-group: pair p=(k>>1)&7 -> 2*(p&3)+(p>>2)
__device__ __forceinline__ int kperm(int k) {
    int p = (k >> 1) & 7;
    return (k & ~15) | ((2 * (p & 3) + (p >> 2)) << 1) | (k & 1);
}

// ---- kernel 0: W -> fp16, k pair-permuted ----
__global__ void prep_w(const float* __restrict__ W) {
    int i = blockIdx.x * blockDim.x + threadIdx.x;
    if (i >= EMBD * KTOT) return;
    g_Wh[(i & ~(KTOT - 1)) | kperm(i & (KTOT - 1))] = __float2half_rn(W[i]);
}

// ---- kernel 1: gather patches -> g_Apack (fp16, k pair-permuted) ----
__global__ void __launch_bounds__(256, 4)
pack_a(const float* __restrict__ img,
       const int*   __restrict__ kp,
       const int*   __restrict__ sh)
{
    __shared__ int2 coord[BM];
    const int tid = threadIdx.x;
    const int wid = tid >> 5;
    const int lid = tid & 31;
    const int m0  = blockIdx.x * BM;

    if (tid < BM) {
        int2 k = ((const int2*)kp)[m0 + tid];
        int2 s = ((const int2*)sh)[m0 + tid];
        int2 c;
        c.x = k.x + s.x - PADC;          // starts[...,0] = x
        c.y = k.y + s.y - PADC;          // starts[...,1] = y
        coord[tid] = c;
    }
    __syncthreads();

    const float* imgb = img + (size_t)(m0 / TDIM) * (HW * HW);
    const int pp = lid & 15;             // pair-slot within 32-half chunk
    const int h  = pp >> 3;              // image row within chunk
    const int jp = pp & 7;               // x-pair
    const int x_off = 2 * jp;
    // permuted position of pair jp within its 16-group (group = row h)
    const int kdst = h * 16 + (2 * (jp & 3) + (jp >> 2)) * 2;

    #pragma unroll 1
    for (int i = 0; i < 8; i++) {
        const int p = i * 16 + wid * 2 + (lid >> 4);
        const int2 c = coord[p];
        __half* orow = g_Apack + (size_t)(m0 + p) * KTOT + kdst;
        #pragma unroll
        for (int kc = 0; kc < 8; kc++) {
            const int y  = c.y + kc * 2 + h;
            const int x0 = c.x + x_off;
            float v0 = 0.f, v1 = 0.f;
            if ((unsigned)y < HW) {
                const float* rp = imgb + y * HW;
                if ((unsigned)(x0)     < HW) v0 = __ldg(rp + x0);
                if ((unsigned)(x0 + 1) < HW) v1 = __ldg(rp + x0 + 1);
            }
            *(__half2*)(orow + kc * 32) = __floats2half2_rn(v0, v1);
        }
    }
}

// ---- kernel 2: dense GEMM out = Apack @ Wh^T + bias ----
__global__ void __launch_bounds__(256, 2)
gemm_tc(const float* __restrict__ bias, float* __restrict__ out)
{
    extern __shared__ char smem[];
    const uint32_t sb = s2u(smem);
    const int tid = threadIdx.x;
    const int wid = tid >> 5;
    const int lid = tid & 31;
    const int m0  = blockIdx.y * BM;
    const int n0  = blockIdx.x * BN;

    const int wm = wid & 3;              // 4 m-groups of 32 rows
    const int wn = wid >> 2;             // 2 n-groups of 64 cols
    const int gq = lid >> 2;             // 0..7
    const int tq = lid & 3;              // 0..3

    float acc[2][8][4] = {};

    // stage load: A rows 0..127 then B rows 0..127; 128B of halves per row
    #define LOAD_STAGE(buf, kc)                                                    \
        {                                                                          \
            _Pragma("unroll")                                                      \
            for (int i = 0; i < 8; i++) {                                          \
                const int idx = i * 256 + tid;          /* 0..2047 */              \
                const int row = (idx >> 3) & 127;                                  \
                const int q   = idx & 7;                                           \
                const uint32_t dst = sb + (i < 4 ? SM_A : SM_B) + (buf) * MATB     \
                                     + row * SROW + q * 16;                        \
                const __half* src = (i < 4)                                        \
                    ? g_Apack + (size_t)(m0 + row) * KTOT + (kc) * BKH + q * 8     \
                    : g_Wh   + (size_t)(n0 + row) * KTOT + (kc) * BKH + q * 8;     \
                cp16(dst, src);                                                    \
            }                                                                      \
            asm volatile("cp.async.commit_group;" ::: "memory");                   \
        }

    LOAD_STAGE(0, 0);
    LOAD_STAGE(1, 1);

    #pragma unroll 1
    for (int kc = 0; kc < NKC; kc++) {
        const int cur = kc & 1;
        if (kc == NKC - 1)
            asm volatile("cp.async.wait_group 0;" ::: "memory");
        else
            asm volatile("cp.async.wait_group 1;" ::: "memory");
        __syncthreads();

        const char* As = smem + SM_A + cur * MATB;
        const char* Bs = smem + SM_B + cur * MATB;

        #pragma unroll
        for (int ks = 0; ks < 4; ks++) {
            const int kb = ks * 32 + 8 * tq;             // byte offset of this thread's pairs
            uint2 a0[2], a1[2];
            #pragma unroll
            for (int mt = 0; mt < 2; mt++) {
                const int r = wm * 32 + mt * 16 + gq;
                a0[mt] = *(const uint2*)(As + r * SROW + kb);        // {a0a1, a4a5}
                a1[mt] = *(const uint2*)(As + (r + 8) * SROW + kb);  // {a2a3, a6a7}
            }
            #pragma unroll
            for (int nt = 0; nt < 8; nt++) {
                const int n = wn * 64 + nt * 8 + gq;
                const uint2 b = *(const uint2*)(Bs + n * SROW + kb); // {b0b1, b2b3}
                mma_f16(acc[0][nt], a0[0].x, a1[0].x, a0[0].y, a1[0].y, b.x, b.y);
                mma_f16(acc[1][nt], a0[1].x, a1[1].x, a0[1].y, a1[1].y, b.x, b.y);
            }
        }

        __syncthreads();
        if (kc + 2 < NKC) LOAD_STAGE(cur, kc + 2);
    }

    // ---- epilogue: bias + float2 stores ----
    #pragma unroll
    for (int mt = 0; mt < 2; mt++) {
        const int r0 = m0 + wm * 32 + mt * 16 + gq;
        #pragma unroll
        for (int nt = 0; nt < 8; nt++) {
            const int col = n0 + wn * 64 + nt * 8 + tq * 2;
            const float2 bl = *(const float2*)(bias + col);
            float2 o0, o1;
            o0.x = acc[mt][nt][0] + bl.x;
            o0.y = acc[mt][nt][1] + bl.y;
            o1.x = acc[mt][nt][2] + bl.x;
            o1.y = acc[mt][nt][3] + bl.y;
            *(float2*)(out + (size_t)r0 * EMBD + col)       = o0;
            *(float2*)(out + (size_t)(r0 + 8) * EMBD + col) = o1;
        }
    }
}

extern "C" void kernel_launch(void* const* d_in, const int* in_sizes, int n_in,
                              void* d_out, int out_size)
{
    const float* img  = (const float*)d_in[0];   // [32,1,512,512] f32
    const int*   kp   = (const int*)  d_in[1];   // [32,4096,2] i32
    const int*   sh   = (const int*)  d_in[2];   // [32,4096,2] i32
    const float* Wlin = (const float*)d_in[3];   // [768,256] f32
    const float* blin = (const float*)d_in[4];   // [768] f32
    float*       out  = (float*)d_out;           // [32,4096,768] f32

    prep_w<<<(EMBD * KTOT + 255) / 256, 256>>>(Wlin);
    pack_a<<<(32 * TDIM) / BM, 256>>>(img, kp, sh);

    cudaFuncSetAttribute(gemm_tc,
                         cudaFuncAttributeMaxDynamicSharedMemorySize, SM_TOTAL);
    dim3 grid(EMBD / BN, (32 * TDIM) / BM);      // (6, 1024)
    gemm_tc<<<grid, 256, SM_TOTAL>>>(blin, out);
}